// round 9
// baseline (speedup 1.0000x reference)
#include <cuda_runtime.h>
#include <cuda_bf16.h>
#include <cstdint>

// Problem constants (fixed by the reference: B=16384, L=512, 3 channels)
#define L_SEQ     512
#define NTHREADS  128
#define PAD_STANCE 3.0f
#define ROW_FLOATS (L_SEQ * 3)          // 1536
#define ROW_BYTES  (ROW_FLOATS * 4)     // 6144, 16B-multiple

// Pads are a strict suffix and valid stance is never 3.0, so
// cumprod(stance != PAD) == (stance != PAD) elementwise.
//
// Stream path: ONE cp.async.bulk (TMA bulk engine) per row into smem — zero
// L1tex wavefronts for the stream. Demux via conflict-free LDS: thread t owns
// positions {t, t+128, t+256, t+384}; within a warp, word addr = 3*lane + c,
// stride 3 coprime with 32 banks -> conflict-free. Gathers via __ldcg
// (L2-only; 4MB table gets ~5% L1 hit anyway).

__device__ __forceinline__ uint32_t smem_u32(const void* p) {
    uint32_t a;
    asm("{ .reg .u64 t; cvta.to.shared.u64 t, %1; cvt.u32.u64 %0, t; }"
        : "=r"(a) : "l"(p));
    return a;
}

__global__ __launch_bounds__(NTHREADS)
void crowd_kernel(const float* __restrict__ in,   // (B, 512, 3) fp32
                  const float* __restrict__ w,    // (1e6,) fp32
                  float* __restrict__ out,        // (6*B,) fp32: pre | dist | theta
                  int B)
{
    __shared__ __align__(16) float buf[ROW_FLOATS];
    __shared__ uint64_t mbar;
    __shared__ float s_real[NTHREADS / 32];
    __shared__ float s_fake[NTHREADS / 32];
    __shared__ float s_cnt [NTHREADS / 32];

    const int b    = blockIdx.x;
    const int tid  = threadIdx.x;
    const int lane = tid & 31;
    const int wrp  = tid >> 5;

    const uint32_t mb = smem_u32(&mbar);
    if (tid == 0) {
        asm volatile("mbarrier.init.shared.b64 [%0], 1;" :: "r"(mb) : "memory");
    }
    __syncthreads();

    if (tid == 0) {
        asm volatile("mbarrier.arrive.expect_tx.shared.b64 _, [%0], %1;"
                     :: "r"(mb), "r"((uint32_t)ROW_BYTES) : "memory");
        asm volatile(
            "cp.async.bulk.shared::cta.global.mbarrier::complete_tx::bytes "
            "[%0], [%1], %2, [%3];"
            :: "r"(smem_u32(buf)),
               "l"(in + (size_t)b * ROW_FLOATS),
               "r"((uint32_t)ROW_BYTES),
               "r"(mb)
            : "memory");
    }

    // Wait for the bulk copy (parity 0; each block uses the barrier once).
    asm volatile(
        "{\n\t"
        ".reg .pred P;\n\t"
        "W%=:\n\t"
        "mbarrier.try_wait.parity.acquire.cta.shared::cta.b64 P, [%0], 0, 0x989680;\n\t"
        "@P bra D%=;\n\t"
        "bra W%=;\n\t"
        "D%=:\n\t"
        "}"
        :: "r"(mb) : "memory");

    // ---- Demux + exact-predicated gathers (conflict-free LDS). ----
    float realp = 0.0f, fakep = 0.0f, cntf = 0.0f;
    #pragma unroll
    for (int k = 0; k < 4; k++) {
        const int p = tid + NTHREADS * k;      // position in [0,512)
        float st = buf[3 * p];                 // LDS, banks 3*lane -> no conflict
        if (st != PAD_STANCE) {
            float g = __ldcg(&w[(int)buf[3 * p + 2]]);   // L2-only gather
            cntf += 1.0f;
            if (st == 0.0f) realp += g;
            else            fakep += g;
        }
    }

    // Warp reduction (3 values share one shuffle ladder).
    #pragma unroll
    for (int off = 16; off > 0; off >>= 1) {
        realp += __shfl_xor_sync(0xFFFFFFFFu, realp, off);
        fakep += __shfl_xor_sync(0xFFFFFFFFu, fakep, off);
        cntf  += __shfl_xor_sync(0xFFFFFFFFu, cntf,  off);
    }
    if (lane == 0) { s_real[wrp] = realp; s_fake[wrp] = fakep; s_cnt[wrp] = cntf; }
    __syncthreads();

    // ---- Epilogue: softmax + Beta moments (thread 0) ----
    if (tid == 0) {
        float rp = s_real[0] + s_real[1] + s_real[2] + s_real[3];
        float fq = s_fake[0] + s_fake[1] + s_fake[2] + s_fake[3];
        float n  = s_cnt[0] + s_cnt[1] + s_cnt[2] + s_cnt[3];

        float m   = fmaxf(rp, fq);
        float e0  = __expf(rp - m);
        float e1  = __expf(fq - m);
        float inv = 1.0f / (e0 + e1);
        float pre0 = e0 * inv;                  // user_pre[:,0] (real)
        float pre1 = e1 * inv;                  // user_pre[:,1] (fake)

        float th0 = pre0 * n;                   // user_theta[:,0] -> beta_b
        float th1 = pre1 * n;                   // user_theta[:,1] -> beta_a
        float a = th1, bb = th0;
        float s = a + bb;
        float mean = a / s;
        float var  = (a * bb) / (s * s * (s + 1.0f));

        // Output layout: tuple-flatten (user_pre, user_distribution, user_theta)
        out[(size_t)b * 2 + 0]                 = pre0;
        out[(size_t)b * 2 + 1]                 = pre1;
        out[(size_t)2 * B + (size_t)b * 2 + 0] = mean;
        out[(size_t)2 * B + (size_t)b * 2 + 1] = sqrtf(var);
        out[(size_t)4 * B + (size_t)b * 2 + 0] = th0;
        out[(size_t)4 * B + (size_t)b * 2 + 1] = th1;
    }
}

extern "C" void kernel_launch(void* const* d_in, const int* in_sizes, int n_in,
                              void* d_out, int out_size)
{
    const float* in = (const float*)d_in[0];   // (B, 512, 3) fp32
    const float* w  = (const float*)d_in[1];   // (1e6,) fp32
    float* out = (float*)d_out;

    int B = in_sizes[0] / ROW_FLOATS;

    crowd_kernel<<<B, NTHREADS>>>(in, w, out, B);
}